// round 5
// baseline (speedup 1.0000x reference)
#include <cuda_runtime.h>
#include <cuda_bf16.h>
#include <cstdint>

// ---------------- problem constants ----------------
#define BB 16
#define QQ 100
#define TT 50
#define GG 16384
#define LL 21
#define KSPLIT 8
#define KPER (GG / KSPLIT)      // 2048
#define KC 64                   // K per stage (64 bf16 = 128B row)
#define NSTAGE (KPER / KC)      // 32
#define NTHREADS 512

// per-stage smem tile offsets (bytes)
#define OFF_AM 0                // 128 rows x 128B bf16 (mask logits)
#define OFF_AS 16384            // 128 rows x 128B bf16 (sigmoid)
#define OFF_Y  32768            // 64 rows x 128B bf16 (targets)
#define STAGE_BYTES 40960
#define SMEM_DYN (2 * STAGE_BYTES)   // 81920

// ---------------- device scratch (no allocation allowed) ----------------
__device__ float g_Dm[BB * QQ * TT];
__device__ float g_Ds[BB * QQ * TT];
__device__ float g_Ssp[BB * QQ];
__device__ float g_Ssg[BB * QQ];
__device__ float g_Sy[BB * TT];

// ---------------- helpers ----------------
__device__ __forceinline__ uint32_t smem_u32(const void* p) {
    uint32_t a;
    asm("{ .reg .u64 t; cvta.to.shared.u64 t, %1; cvt.u32.u64 %0, t; }"
        : "=r"(a) : "l"(p));
    return a;
}
__device__ __forceinline__ uint32_t swz128(uint32_t off) {
    return off ^ ((off >> 3) & 0x70u);
}
__device__ __forceinline__ uint32_t lds32(uint32_t addr) {
    uint32_t v;
    asm volatile("ld.shared.b32 %0, [%1];" : "=r"(v) : "r"(addr));
    return v;
}
// softplus + sigmoid: 3 MUFU (EX2, RCP, LG2)
__device__ __forceinline__ void act(float v, float& sp, float& sg) {
    float a = fabsf(v);
    float e = __expf(-a);
    float u = 1.0f + e;
    float r;
    asm("rcp.approx.f32 %0, %1;" : "=f"(r) : "f"(u));
    sg = (v >= 0.0f) ? r : (1.0f - r);
    float lg;
    asm("lg2.approx.f32 %0, %1;" : "=f"(lg) : "f"(u));
    sp = lg * 0.6931471805599453f + fmaxf(v, 0.0f);
}
__device__ __forceinline__ float red8(float v) {
#pragma unroll
    for (int d = 4; d; d >>= 1) v += __shfl_down_sync(0xFFFFFFFFu, v, d);
    return v;
}

// ---------------- zero scratch ----------------
__global__ void matcher_zero() {
    int i = blockIdx.x * blockDim.x + threadIdx.x;
    if (i < BB * QQ * TT) { g_Dm[i] = 0.0f; g_Ds[i] = 0.0f; }
    if (i < BB * QQ) { g_Ssp[i] = 0.0f; g_Ssg[i] = 0.0f; }
    if (i < BB * TT) { g_Sy[i] = 0.0f; }
}

// ---------------- main: activations + split-K HMMA GEMMs ----------------
__global__ void __launch_bounds__(NTHREADS, 1)
matcher_main(const float* __restrict__ m, const float* __restrict__ y) {
    extern __shared__ char smem[];
    uint32_t sb = smem_u32(smem);
    int tid = threadIdx.x;
    int wid = tid >> 5;
    int lid = tid & 31;
    int b = blockIdx.x / KSPLIT;
    int ks = blockIdx.x % KSPLIT;
    int g0 = ks * KPER;

    // zero both stage buffers once (pad rows A[100:128), Y[50:64) must stay 0)
    {
        uint4 z = make_uint4(0u, 0u, 0u, 0u);
        for (int i = tid; i < SMEM_DYN / 16; i += NTHREADS)
            reinterpret_cast<uint4*>(smem)[i] = z;
    }
    __syncthreads();

    // fill-role: 8 threads per row, 8 consecutive floats each
    int r0 = tid >> 3;          // 0..63
    int r1 = 64 + r0;           // 64..127 (valid < 100)
    int cb = (tid & 7) * 8;
    bool h1 = (r1 < QQ);
    bool hy = (r0 < TT);
    const float* mrow0 = m + (size_t)(b * QQ + r0) * GG + g0 + cb;
    const float* mrow1 = m + (size_t)(b * QQ + (h1 ? r1 : 0)) * GG + g0 + cb;
    const float* yrow  = y + (size_t)(b * TT + (hy ? r0 : 0)) * GG + g0 + cb;
    uint32_t so  = swz128((uint32_t)(r0 * 128 + cb * 2));
    uint32_t so1 = swz128((uint32_t)(r1 * 128 + cb * 2));

    float sp0 = 0.f, sg0 = 0.f, sp1 = 0.f, sg1 = 0.f, syp = 0.f;
    float f0[8], f1[8], fy[8];

    auto loadG = [&](int it) {
        int gk = it * KC;
        float4 u0 = *(const float4*)(mrow0 + gk);
        float4 u1 = *(const float4*)(mrow0 + gk + 4);
        f0[0] = u0.x; f0[1] = u0.y; f0[2] = u0.z; f0[3] = u0.w;
        f0[4] = u1.x; f0[5] = u1.y; f0[6] = u1.z; f0[7] = u1.w;
        if (h1) {
            float4 v0 = *(const float4*)(mrow1 + gk);
            float4 v1 = *(const float4*)(mrow1 + gk + 4);
            f1[0] = v0.x; f1[1] = v0.y; f1[2] = v0.z; f1[3] = v0.w;
            f1[4] = v1.x; f1[5] = v1.y; f1[6] = v1.z; f1[7] = v1.w;
        }
        if (hy) {
            float4 w0 = *(const float4*)(yrow + gk);
            float4 w1 = *(const float4*)(yrow + gk + 4);
            fy[0] = w0.x; fy[1] = w0.y; fy[2] = w0.z; fy[3] = w0.w;
            fy[4] = w1.x; fy[5] = w1.y; fy[6] = w1.z; fy[7] = w1.w;
        }
    };

    auto storeS = [&](int buf) {
        char* stg = smem + buf * STAGE_BYTES;
        uint32_t pm[4], ps[4];
#pragma unroll
        for (int i = 0; i < 4; ++i) {
            float sa, ga, sc, gc;
            act(f0[2 * i], sa, ga);
            act(f0[2 * i + 1], sc, gc);
            sp0 += sa + sc; sg0 += ga + gc;
            __nv_bfloat162 hm = __floats2bfloat162_rn(f0[2 * i], f0[2 * i + 1]);
            __nv_bfloat162 hs = __floats2bfloat162_rn(ga, gc);
            pm[i] = *reinterpret_cast<uint32_t*>(&hm);
            ps[i] = *reinterpret_cast<uint32_t*>(&hs);
        }
        *(uint4*)(stg + OFF_AM + so) = make_uint4(pm[0], pm[1], pm[2], pm[3]);
        *(uint4*)(stg + OFF_AS + so) = make_uint4(ps[0], ps[1], ps[2], ps[3]);
        if (h1) {
#pragma unroll
            for (int i = 0; i < 4; ++i) {
                float sa, ga, sc, gc;
                act(f1[2 * i], sa, ga);
                act(f1[2 * i + 1], sc, gc);
                sp1 += sa + sc; sg1 += ga + gc;
                __nv_bfloat162 hm = __floats2bfloat162_rn(f1[2 * i], f1[2 * i + 1]);
                __nv_bfloat162 hs = __floats2bfloat162_rn(ga, gc);
                pm[i] = *reinterpret_cast<uint32_t*>(&hm);
                ps[i] = *reinterpret_cast<uint32_t*>(&hs);
            }
            *(uint4*)(stg + OFF_AM + so1) = make_uint4(pm[0], pm[1], pm[2], pm[3]);
            *(uint4*)(stg + OFF_AS + so1) = make_uint4(ps[0], ps[1], ps[2], ps[3]);
        }
        if (hy) {
            uint32_t py[4];
#pragma unroll
            for (int i = 0; i < 4; ++i) {
                syp += fy[2 * i] + fy[2 * i + 1];
                __nv_bfloat162 h2 = __floats2bfloat162_rn(fy[2 * i], fy[2 * i + 1]);
                py[i] = *reinterpret_cast<uint32_t*>(&h2);
            }
            *(uint4*)(stg + OFF_Y + so) = make_uint4(py[0], py[1], py[2], py[3]);
        }
    };

    // mma-role: warps 0-6 -> D_m strips, warps 7-13 -> D_s strips
    const bool cw = (wid < 14);
    const int gsel = (wid >= 7) ? 1 : 0;
    const int mt = gsel ? (wid - 7) : wid;
    const int gq = lid >> 2;          // 0..7
    const int tig = lid & 3;          // 0..3
    float acc[7][4];
#pragma unroll
    for (int nt = 0; nt < 7; ++nt)
#pragma unroll
        for (int i = 0; i < 4; ++i) acc[nt][i] = 0.0f;

    auto mmaStage = [&](int buf) {
        if (!cw) return;
        uint32_t base = sb + (uint32_t)(buf * STAGE_BYTES);
        uint32_t abase = base + (gsel ? OFF_AS : OFF_AM);
        uint32_t ybase = base + OFF_Y;
        uint32_t rlo = (uint32_t)((mt * 16 + gq) * 128);
        uint32_t rhi = rlo + 8 * 128;
#pragma unroll
        for (int kc = 0; kc < 4; ++kc) {
            uint32_t co = (uint32_t)(kc * 32 + tig * 4);
            uint32_t a0 = lds32(abase + swz128(rlo + co));
            uint32_t a1 = lds32(abase + swz128(rhi + co));
            uint32_t a2 = lds32(abase + swz128(rlo + co + 16));
            uint32_t a3 = lds32(abase + swz128(rhi + co + 16));
#pragma unroll
            for (int nt = 0; nt < 7; ++nt) {
                uint32_t yr = (uint32_t)((nt * 8 + gq) * 128);
                uint32_t b0 = lds32(ybase + swz128(yr + co));
                uint32_t b1 = lds32(ybase + swz128(yr + co + 16));
                asm volatile(
                    "mma.sync.aligned.m16n8k16.row.col.f32.bf16.bf16.f32 "
                    "{%0,%1,%2,%3}, {%4,%5,%6,%7}, {%8,%9}, {%0,%1,%2,%3};"
                    : "+f"(acc[nt][0]), "+f"(acc[nt][1]),
                      "+f"(acc[nt][2]), "+f"(acc[nt][3])
                    : "r"(a0), "r"(a1), "r"(a2), "r"(a3), "r"(b0), "r"(b1));
            }
        }
    };

    // software pipeline: loadG(it+1) | mma(it) | storeS(it+1) | barrier
    loadG(0);
    storeS(0);
    __syncthreads();
#pragma unroll 1
    for (int it = 0; it < NSTAGE; ++it) {
        if (it + 1 < NSTAGE) loadG(it + 1);
        mmaStage(it & 1);
        if (it + 1 < NSTAGE) storeS((it + 1) & 1);
        __syncthreads();
    }

    // ---- row-sum partials ----
    sp0 = red8(sp0); sg0 = red8(sg0);
    sp1 = red8(sp1); sg1 = red8(sg1);
    syp = red8(syp);
    if ((tid & 7) == 0) {
        atomicAdd(&g_Ssp[b * QQ + r0], sp0);
        atomicAdd(&g_Ssg[b * QQ + r0], sg0);
        if (h1) {
            atomicAdd(&g_Ssp[b * QQ + r1], sp1);
            atomicAdd(&g_Ssg[b * QQ + r1], sg1);
        }
        if (hy) atomicAdd(&g_Sy[b * TT + r0], syp);
    }

    // ---- D partial accumulation ----
    if (cw) {
        float* dst = gsel ? g_Ds : g_Dm;
        int rlo_i = mt * 16 + gq;
        int rhi_i = rlo_i + 8;
#pragma unroll
        for (int nt = 0; nt < 7; ++nt) {
            int c0 = nt * 8 + tig * 2;
            int c1 = c0 + 1;
            if (rlo_i < QQ) {
                if (c0 < TT) atomicAdd(&dst[(b * QQ + rlo_i) * TT + c0], acc[nt][0]);
                if (c1 < TT) atomicAdd(&dst[(b * QQ + rlo_i) * TT + c1], acc[nt][1]);
            }
            if (rhi_i < QQ) {
                if (c0 < TT) atomicAdd(&dst[(b * QQ + rhi_i) * TT + c0], acc[nt][2]);
                if (c1 < TT) atomicAdd(&dst[(b * QQ + rhi_i) * TT + c1], acc[nt][3]);
            }
        }
    }
}

// ---------------- epilogue: class softmax + combine ----------------
__global__ void matcher_epi(const float* __restrict__ cl,
                            const int* __restrict__ lab32,
                            float* __restrict__ out) {
    int b = blockIdx.x;
    int q = threadIdx.x;
    __shared__ int s_i64;
    if (q == 0) {
        // int64 labels: odd 32-bit words all 0, even words in [0, L)
        int ok = 1;
        for (int k = 0; k < 64; ++k) {
            int lo = lab32[2 * k], hi = lab32[2 * k + 1];
            if (hi != 0 || lo < 0 || lo >= LL) { ok = 0; break; }
        }
        s_i64 = ok;
    }
    __syncthreads();
    if (q >= QQ) return;

    const float* c = cl + (size_t)(b * QQ + q) * LL;
    float mx = -1e30f;
#pragma unroll
    for (int l = 0; l < LL; ++l) mx = fmaxf(mx, c[l]);
    float s = 0.0f;
#pragma unroll
    for (int l = 0; l < LL; ++l) s += __expf(c[l] - mx);
    float inv = 1.0f / s;

    float ssp = g_Ssp[b * QQ + q];
    float ssg = g_Ssg[b * QQ + q];
    const float invG = 1.0f / (float)GG;
    int i64 = s_i64;

    for (int t = 0; t < TT; ++t) {
        int idx = b * TT + t;
        int lbl = i64 ? lab32[2 * idx] : lab32[idx];
        float p = __expf(c[lbl] - mx) * inv;
        float dm = g_Dm[(b * QQ + q) * TT + t];
        float ds = g_Ds[(b * QQ + q) * TT + t];
        float sy = g_Sy[idx];
        float dice = 1.0f - (2.0f * ds + 1.0f) / (ssg + sy + 1.0f);
        float cost = (ssp - dm) * invG - p + dice;
        out[(b * QQ + q) * TT + t] = cost;
    }
}

// ---------------- launch ----------------
extern "C" void kernel_launch(void* const* d_in, const int* in_sizes, int n_in,
                              void* d_out, int out_size) {
    (void)in_sizes; (void)n_in; (void)out_size;
    const float* m = (const float*)d_in[0];
    const float* cl = (const float*)d_in[1];
    const float* y = (const float*)d_in[2];
    const int* lab = (const int*)d_in[3];
    float* out = (float*)d_out;

    cudaFuncSetAttribute(matcher_main,
                         cudaFuncAttributeMaxDynamicSharedMemorySize, SMEM_DYN);

    matcher_zero<<<(BB * QQ * TT + 255) / 256, 256>>>();
    matcher_main<<<BB * KSPLIT, NTHREADS, SMEM_DYN>>>(m, y);
    matcher_epi<<<BB, 128>>>(cl, lab, out);
}